// round 14
// baseline (speedup 1.0000x reference)
#include <cuda_runtime.h>
#include <cuda_fp16.h>
#include <cstdint>
#include <math.h>

// Problem constants
#define BATCH 4096
#define D_IN  1024
#define DF    256
#define NM    10
#define NK    8
#define NMK   80
#define LOG2PI_F 1.8378770664093453f

// ---------------- scratch (no cudaMalloc allowed) ----------------
__device__ __align__(16) float  g_Ainv[NMK * DF * DF]; // fp32 L^-1 (upper zeroed)
__device__ __align__(16) __half g_xh[BATCH * D_IN];    // x fp16, [b][k]
__device__ __align__(16) __half g_Wh[DF * D_IN];       // W^T fp16, [n][k]
__device__ __align__(16) __half g_fh[BATCH * DF];      // feats fp16, [b][d]
__device__ __align__(16) __half g_Bh[NMK * DF * DF];   // Ainv fp16, [mk][d][k]
__device__ float g_v[NMK * DF];                         // Ainv @ mean (fp32)
__device__ float g_c1[NMK];                             // -0.5 * w
__device__ float g_c2[NMK];                             // w*(-0.5*DF*log2pi) - w*logdet

// quad chunk schedule: 10 K=64 chunks, dblk-major
__constant__ int c_CD4[10] = {0, 1,1, 2,2,2, 3,3,3,3};
__constant__ int c_CK4[10] = {0, 0,1, 0,1,2, 0,1,2,3};

// ---------------- helpers ----------------
__device__ __forceinline__ uint32_t smem_u32(const void* p) {
    uint32_t a;
    asm("{ .reg .u64 t; cvta.to.shared.u64 t, %1; cvt.u32.u64 %0, t; }" : "=r"(a) : "l"(p));
    return a;
}

#define LDSM4(r, addr) \
    asm volatile("ldmatrix.sync.aligned.m8n8.x4.shared.b16 {%0,%1,%2,%3}, [%4];" \
        : "=r"((r)[0]), "=r"((r)[1]), "=r"((r)[2]), "=r"((r)[3]) : "r"(addr))

#define MMA16816(d, a, b) \
    asm volatile("mma.sync.aligned.m16n8k16.row.col.f32.f16.f16.f32 " \
        "{%0,%1,%2,%3},{%4,%5,%6,%7},{%8,%9},{%0,%1,%2,%3};" \
        : "+f"((d)[0]), "+f"((d)[1]), "+f"((d)[2]), "+f"((d)[3]) \
        : "r"((a)[0]), "r"((a)[1]), "r"((a)[2]), "r"((a)[3]), "r"((b)[0]), "r"((b)[1]))

#define CP16(saddr, gptr) \
    asm volatile("cp.async.cg.shared.global [%0], [%1], 16;" :: "r"(saddr), "l"(gptr) : "memory")
#define CP_COMMIT() asm volatile("cp.async.commit_group;" ::: "memory")
#define CP_WAIT1()  asm volatile("cp.async.wait_group 1;" ::: "memory")
#define CP_WAIT0()  asm volatile("cp.async.wait_group 0;" ::: "memory")

// feats stage buffer (24 KB per stage): F 128x128B @0, W 64x128B @16384
#define STG_SZ   24576
#define STG_FH   0
#define STG_WH   16384

// quad smem: persistent F [128 rows x 512B] @0 (64KB),
//            A ring 2 x 16KB @65536 (per stage: 2 mk x 64 rows x 128B),
//            V @98304 (512 f), Q @100352 (512 f: [mk][n2][128])
#define ST4_F    0
#define ST4_A    65536
#define A_STG_SZ 16384
#define OFQ4_V   98304
#define OFQ4_Q   100352
#define QUAD4_SMEM 102400

// ---------------------------------------------------------------------------
// split kernels (fp32 -> fp16)
// ---------------------------------------------------------------------------
__global__ __launch_bounds__(256) void k_xsplit(const float* __restrict__ x)
{
    size_t idx = ((size_t)blockIdx.x * 256 + threadIdx.x) * 4;
    float4 v = *(const float4*)&x[idx];
    *(__half2*)&g_xh[idx]     = __floats2half2_rn(v.x, v.y);
    *(__half2*)&g_xh[idx + 2] = __floats2half2_rn(v.z, v.w);
}

// W [k][n] fp32 -> W^T [n][k] fp16 via smem 32x32 transpose
__global__ __launch_bounds__(256) void k_wsplit(const float* __restrict__ W)
{
    __shared__ float t[32][33];
    const int k0 = blockIdx.x * 32;
    const int n0 = blockIdx.y * 32;
    const int tx = threadIdx.x & 31, ty = threadIdx.x >> 5;
#pragma unroll
    for (int i = 0; i < 4; i++)
        t[ty + i * 8][tx] = W[(size_t)(k0 + ty + i * 8) * DF + n0 + tx];
    __syncthreads();
#pragma unroll
    for (int i = 0; i < 4; i++) {
        int n = n0 + ty + i * 8;
        g_Wh[(size_t)n * D_IN + k0 + tx] = __float2half_rn(t[tx][ty + i * 8]);
    }
}

// ---------------------------------------------------------------------------
// k_feats_mma: feats = relu(x @ W + b), single-pass fp16 warp-MMA. (unchanged)
// ---------------------------------------------------------------------------
__global__ __launch_bounds__(256) void k_feats_mma(const float* __restrict__ bias)
{
    extern __shared__ char sm[];
    const uint32_t smb = smem_u32(sm);
    const int tid = threadIdx.x;
    const int lane = tid & 31;
    const int wid = tid >> 5;
    const int warp_m = wid >> 1;
    const int warp_n = wid & 1;
    const int b0 = blockIdx.x * 128;
    const int n0 = blockIdx.y * 64;

    const __half* fh = g_xh + (size_t)b0 * D_IN;
    const __half* ah = g_Wh + (size_t)n0 * D_IN;

    const int aRow[2] = { warp_m * 32 +  0 + (lane & 7) + ((lane >> 3) & 1) * 8,
                          warp_m * 32 + 16 + (lane & 7) + ((lane >> 3) & 1) * 8 };
    const int aG = (lane >> 4) & 1;
    const int bRow[2] = { warp_n * 32 +  0 + (lane & 7) + ((lane >> 4) & 1) * 8,
                          warp_n * 32 + 16 + (lane & 7) + ((lane >> 4) & 1) * 8 };
    const int bG = (lane >> 3) & 1;
    const int aXor[2] = { aRow[0] & 7, aRow[1] & 7 };
    const int bXor[2] = { bRow[0] & 7, bRow[1] & 7 };

    auto stage = [&](int j) {
        const uint32_t sb = smb + (uint32_t)(j & 1) * STG_SZ;
        const int k0 = j * 64;
#pragma unroll
        for (int it = 0; it < 4; it++) {
            int slot = tid + it * 256;
            int row = slot >> 3, g = slot & 7;
            uint32_t off = (uint32_t)(row * 128 + ((g ^ (row & 7)) << 4));
            CP16(sb + STG_FH + off, fh + (size_t)row * D_IN + k0 + g * 8);
        }
#pragma unroll
        for (int it = 0; it < 2; it++) {
            int slot = tid + it * 256;
            int row = slot >> 3, g = slot & 7;
            uint32_t off = (uint32_t)(row * 128 + ((g ^ (row & 7)) << 4));
            CP16(sb + STG_WH + off, ah + (size_t)row * D_IN + k0 + g * 8);
        }
        CP_COMMIT();
    };

    float acc[2][4][4];
#pragma unroll
    for (int mt = 0; mt < 2; mt++)
#pragma unroll
        for (int nt = 0; nt < 4; nt++)
#pragma unroll
            for (int r = 0; r < 4; r++) acc[mt][nt][r] = 0.f;

    stage(0);
#pragma unroll 1
    for (int ci = 0; ci < 16; ci++) {
        if (ci + 1 < 16) { stage(ci + 1); CP_WAIT1(); } else { CP_WAIT0(); }
        __syncthreads();
        const uint32_t sb = smb + (uint32_t)(ci & 1) * STG_SZ;
#pragma unroll
        for (int ks = 0; ks < 4; ks++) {
            uint32_t fa[2][4], bm[2][4];
#pragma unroll
            for (int mt = 0; mt < 2; mt++) {
                uint32_t ga = (uint32_t)(((ks * 2 + aG) ^ aXor[mt]) << 4);
                LDSM4(fa[mt], sb + STG_FH + aRow[mt] * 128 + ga);
            }
#pragma unroll
            for (int pr = 0; pr < 2; pr++) {
                uint32_t gb = (uint32_t)(((ks * 2 + bG) ^ bXor[pr]) << 4);
                LDSM4(bm[pr], sb + STG_WH + bRow[pr] * 128 + gb);
            }
#pragma unroll
            for (int mt = 0; mt < 2; mt++)
#pragma unroll
                for (int nt = 0; nt < 4; nt++)
                    MMA16816(acc[mt][nt], fa[mt], &bm[nt >> 1][(nt & 1) * 2]);
        }
        __syncthreads();
    }

#pragma unroll
    for (int nt = 0; nt < 4; nt++) {
        int c = n0 + warp_n * 32 + nt * 8 + (lane & 3) * 2;
        float bc0 = bias[c], bc1 = bias[c + 1];
#pragma unroll
        for (int mt = 0; mt < 2; mt++) {
#pragma unroll
            for (int half = 0; half < 2; half++) {
                int row = b0 + warp_m * 32 + mt * 16 + (lane >> 2) + half * 8;
                float v0 = acc[mt][nt][half * 2 + 0] + bc0;
                float v1 = acc[mt][nt][half * 2 + 1] + bc1;
                v0 = v0 > 0.f ? v0 : 0.f;
                v1 = v1 > 0.f ? v1 : 0.f;
                *(__half2*)&g_fh[(size_t)row * DF + c] = __floats2half2_rn(v0, v1);
            }
        }
    }
}

// ---------------------------------------------------------------------------
// Kernel: triangular inverse of L; writes fp32 g_Ainv AND fp16 g_Bh.
// ---------------------------------------------------------------------------
__global__ __launch_bounds__(256) void k_trinv(const float* __restrict__ covs)
{
    const int mk = blockIdx.x;
    const int cg = blockIdx.y;
    const int w = threadIdx.x >> 5;
    const int lane = threadIdx.x & 31;
    const int g = w * 8 + cg;
    const int j0 = g * 4;

    const float* L = covs + (size_t)mk * DF * DF;
    float* Ai = g_Ainv + (size_t)mk * DF * DF;
    __half* Bh = g_Bh + (size_t)mk * DF * DF;

    __shared__ float4 xck[8][DF];
    float4* xc = xck[w];

    for (int i = lane; i < j0; i += 32) {
        *(float4*)&Ai[i * DF + j0] = make_float4(0.f, 0.f, 0.f, 0.f);
        __half2 z2 = __floats2half2_rn(0.f, 0.f);
        *(__half2*)&Bh[i * DF + j0]     = z2;
        *(__half2*)&Bh[i * DF + j0 + 2] = z2;
    }

    for (int i = j0; i < DF; i++) {
        float4 s = make_float4(0.f, 0.f, 0.f, 0.f);
        for (int k = j0 + lane; k < i; k += 32) {
            float lik = L[i * DF + k];
            float4 xv = xc[k];
            s.x = fmaf(lik, xv.x, s.x);
            s.y = fmaf(lik, xv.y, s.y);
            s.z = fmaf(lik, xv.z, s.z);
            s.w = fmaf(lik, xv.w, s.w);
        }
#pragma unroll
        for (int off = 16; off > 0; off >>= 1) {
            s.x += __shfl_xor_sync(0xFFFFFFFFu, s.x, off);
            s.y += __shfl_xor_sync(0xFFFFFFFFu, s.y, off);
            s.z += __shfl_xor_sync(0xFFFFFFFFu, s.z, off);
            s.w += __shfl_xor_sync(0xFFFFFFFFu, s.w, off);
        }
        if (lane == 0) {
            float inv = 1.0f / L[i * DF + i];
            float4 xr;
            xr.x = ((i == j0 + 0 ? 1.0f : 0.0f) - s.x) * inv;
            xr.y = ((i == j0 + 1 ? 1.0f : 0.0f) - s.y) * inv;
            xr.z = ((i == j0 + 2 ? 1.0f : 0.0f) - s.z) * inv;
            xr.w = ((i == j0 + 3 ? 1.0f : 0.0f) - s.w) * inv;
            xc[i] = xr;
            *(float4*)&Ai[i * DF + j0] = xr;
            *(__half2*)&Bh[i * DF + j0]     = __floats2half2_rn(xr.x, xr.y);
            *(__half2*)&Bh[i * DF + j0 + 2] = __floats2half2_rn(xr.z, xr.w);
        }
        __syncwarp();
    }
}

// ---------------------------------------------------------------------------
// Kernel: v[mk][d] = sum_k Ainv[mk][d][k] * mean[mk][k]  (grid (80,4))
// ---------------------------------------------------------------------------
__global__ __launch_bounds__(256) void k_vprep(const float* __restrict__ means)
{
    const int mk = blockIdx.x;
    const int d0 = blockIdx.y * 64;
    const int tid = threadIdx.x;
    const int w = tid >> 5;
    const int lane = tid & 31;
    __shared__ float ms[DF];
    ms[tid] = means[mk * DF + tid];
    __syncthreads();
    const float* Ai = g_Ainv + (size_t)mk * DF * DF;
    for (int d = d0 + w; d < d0 + 64; d += 8) {
        float s = 0.0f;
        for (int k = lane; k < DF; k += 32)
            s = fmaf(Ai[d * DF + k], ms[k], s);
#pragma unroll
        for (int off = 16; off > 0; off >>= 1)
            s += __shfl_xor_sync(0xFFFFFFFFu, s, off);
        if (lane == 0) g_v[mk * DF + d] = s;
    }
}

// ---------------------------------------------------------------------------
// Kernel: per-component constants, one warp per mk (grid 80, block 32)
// ---------------------------------------------------------------------------
__global__ __launch_bounds__(32) void k_prep(const float* __restrict__ covs,
                                             const float* __restrict__ weights)
{
    const int mk = blockIdx.x;
    const int lane = threadIdx.x;
    const float* L = covs + (size_t)mk * DF * DF;
    float logdet = 0.0f;
    for (int i = lane; i < DF; i += 32)
        logdet += logf(L[i * DF + i]);
#pragma unroll
    for (int off = 16; off > 0; off >>= 1)
        logdet += __shfl_xor_sync(0xFFFFFFFFu, logdet, off);
    if (lane == 0) {
        const int m = mk >> 3;
        float wk[NK];
        float mx = -1e30f;
#pragma unroll
        for (int j = 0; j < NK; j++) { wk[j] = weights[m * NK + j]; mx = fmaxf(mx, wk[j]); }
        float sum = 0.f;
#pragma unroll
        for (int j = 0; j < NK; j++) sum += expf(wk[j] - mx);
        float wsm = expf(weights[mk] - mx) / sum;
        g_c1[mk] = -0.5f * wsm;
        g_c2[mk] = wsm * (-0.5f * (float)DF * LOG2PI_F) - wsm * logdet;
    }
}

// ---------------------------------------------------------------------------
// Kernel (hot): fp16 warp-MMA + fused Mahalanobis epilogue.
// 512 threads, 16 warps: warp tile 32(m) x 32(n of one mk) -> 32 acc regs/warp.
// warp_m = wid&3 (32 rows), warp_n2 = (wid>>2)&1 (col half), warp_mk = wid>>3.
// Persistent F (staged once); A in 10 K=64 chunks, 2-stage ring, tri skip.
// ---------------------------------------------------------------------------
__global__ __launch_bounds__(512, 2) void k_quad_mma(float* __restrict__ out)
{
    extern __shared__ char sm[];
    const uint32_t smb = smem_u32(sm);
    const int tid = threadIdx.x;
    const int lane = tid & 31;
    const int wid = tid >> 5;
    const int warp_m  = wid & 3;        // 0..3  (32 batch rows)
    const int warp_n2 = (wid >> 2) & 1; // 0..1  (32-col half of the mk)
    const int warp_mk = wid >> 3;       // 0..1
    const int mk0 = blockIdx.y * 2;
    const int b0 = blockIdx.x * 128;

    ((float*)(sm + OFQ4_V))[tid] = g_v[mk0 * DF + tid];  // 512 = both mk

    const __half* fh = g_fh + (size_t)b0 * DF;
    const __half* ap[2] = { g_Bh + (size_t)mk0 * DF * DF,
                            g_Bh + (size_t)(mk0 + 1) * DF * DF };

    // ---- stage persistent F: 128 rows x 32 groups of 16B, swizzled ----
#pragma unroll
    for (int it = 0; it < 8; it++) {
        int u = tid + it * 512;          // 0..4095
        int r = u >> 5, g = u & 31;
        uint32_t off = (uint32_t)(r * 512 + (((g & 24) | ((g & 7) ^ (r & 7))) << 4));
        CP16(smb + ST4_F + off, fh + (size_t)r * DF + g * 8);
    }
    CP_COMMIT();   // F group drains with the first A-chunk wait

    // F ldmatrix lane addressing
    int rA[2];
#pragma unroll
    for (int mt = 0; mt < 2; mt++)
        rA[mt] = warp_m * 32 + mt * 16 + (lane & 7) + ((lane >> 3) & 1) * 8;
    const int gselA = (lane >> 4) & 1;

    // A ldmatrix lane addressing: this warp's 32 cols = rows warp_n2*32.. of A
    int rB[2];
#pragma unroll
    for (int pr = 0; pr < 2; pr++)
        rB[pr] = warp_n2 * 32 + pr * 16 + (lane & 7) + ((lane >> 4) & 1) * 8;
    const int gselB = (lane >> 3) & 1;

    auto stageA = [&](int j) {
        const uint32_t sb = smb + ST4_A + (uint32_t)(j & 1) * A_STG_SZ;
        const int k0 = c_CK4[j] * 64;
        const int ar0 = c_CD4[j] * 64;
        const bool diag = (c_CK4[j] == c_CD4[j]);
#pragma unroll
        for (int it = 0; it < 2; it++) {
            int u = tid + it * 512;             // 0..1023
            int mki = u >> 9;
            int v = u & 511;
            int r = v >> 3, g = v & 7;          // A row 0..63, 16B group 0..7
            // diag chunk: stage only 16x16 tiles on/below diagonal
            if (!diag || ((g >> 1) <= (r >> 4))) {
                uint32_t off = (uint32_t)(r * 128 + ((g ^ (r & 7)) << 4));
                CP16(sb + mki * 8192 + off,
                     ap[mki] + (size_t)(ar0 + r) * DF + k0 + g * 8);
            }
        }
        CP_COMMIT();
    };

    float qrow[4] = {0.f, 0.f, 0.f, 0.f};
    const float* vptr = (const float*)(sm + OFQ4_V) + warp_mk * DF;

    stageA(0);
    int ci = 0;
#pragma unroll 1
    for (int dblk = 0; dblk < 4; dblk++) {
        const int nrow0 = dblk * 64;
        const int nch = dblk + 1;
        float acc[2][4][4];
#pragma unroll
        for (int mt = 0; mt < 2; mt++)
#pragma unroll
            for (int nt = 0; nt < 4; nt++)
#pragma unroll
                for (int r = 0; r < 4; r++) acc[mt][nt][r] = 0.f;

#pragma unroll 1
        for (int kc = 0; kc < nch; kc++) {
            if (ci + 1 < 10) { stageA(ci + 1); CP_WAIT1(); } else { CP_WAIT0(); }
            __syncthreads();
            const uint32_t sbA = smb + ST4_A + (uint32_t)(ci & 1) * A_STG_SZ
                               + (uint32_t)warp_mk * 8192;
            const int ck = c_CK4[ci];
            const bool diag = (kc == nch - 1);   // kc == dblk
#pragma unroll
            for (int ks = 0; ks < 4; ks++) {
                uint32_t fa[2][4];
#pragma unroll
                for (int mt = 0; mt < 2; mt++) {
                    int g = ck * 8 + ks * 2 + gselA;
                    uint32_t off = (uint32_t)(rA[mt] * 512 +
                        (((g & 24) | ((g & 7) ^ (rA[mt] & 7))) << 4));
                    LDSM4(fa[mt], smb + ST4_F + off);
                }
#pragma unroll
                for (int pr = 0; pr < 2; pr++) {
                    if (!diag || (warp_n2 * 2 + pr) >= ks) {
                        uint32_t bm[4];
                        uint32_t offb = (uint32_t)(rB[pr] * 128 +
                            (((ks * 2 + gselB) ^ (rB[pr] & 7)) << 4));
                        LDSM4(bm, sbA + offb);
#pragma unroll
                        for (int mt = 0; mt < 2; mt++)
#pragma unroll
                            for (int j2 = 0; j2 < 2; j2++)
                                MMA16816(acc[mt][pr * 2 + j2], fa[mt], &bm[j2 * 2]);
                    }
                }
            }
            __syncthreads();
            ci++;
        }

        // fold: z = D - v[d]; qrow += z^2 (this warp's 32 cols of its mk)
#pragma unroll
        for (int mt = 0; mt < 2; mt++)
#pragma unroll
            for (int nt = 0; nt < 4; nt++) {
#pragma unroll
                for (int r = 0; r < 4; r++) {
                    int d = nrow0 + warp_n2 * 32 + nt * 8 + (lane & 3) * 2 + (r & 1);
                    float z = acc[mt][nt][r] - vptr[d];
                    qrow[mt * 2 + (r >> 1)] = fmaf(z, z, qrow[mt * 2 + (r >> 1)]);
                }
            }
    }

    // reduce 4 lanes/row, then write per (mk, n2) partials; final sum below
    float* qs = (float*)(sm + OFQ4_Q);   // [mk][n2][128]
#pragma unroll
    for (int i = 0; i < 4; i++) {
        float q = qrow[i];
        q += __shfl_xor_sync(0xFFFFFFFFu, q, 1);
        q += __shfl_xor_sync(0xFFFFFFFFu, q, 2);
        if ((lane & 3) == 0) {
            int row = warp_m * 32 + (i >> 1) * 16 + (i & 1) * 8 + (lane >> 2);
            qs[warp_mk * 256 + warp_n2 * 128 + row] = q;
        }
    }
    __syncthreads();
    if (tid < 256) {
        int mkloc = tid >> 7;
        int row = tid & 127;
        int mk = mk0 + mkloc;
        float tot = qs[mkloc * 256 + row] + qs[mkloc * 256 + 128 + row];
        out[(size_t)(b0 + row) * NMK + mk] = fmaf(g_c1[mk], tot, g_c2[mk]);
    }
}

// ---------------------------------------------------------------------------
extern "C" void kernel_launch(void* const* d_in, const int* in_sizes, int n_in,
                              void* d_out, int out_size)
{
    const float* x       = (const float*)d_in[0];
    const float* W       = (const float*)d_in[1];
    const float* bias    = (const float*)d_in[2];
    const float* means   = (const float*)d_in[3];
    const float* covs    = (const float*)d_in[4];
    const float* weights = (const float*)d_in[5];
    float* out = (float*)d_out;

    cudaFuncSetAttribute(k_quad_mma, cudaFuncAttributeMaxDynamicSharedMemorySize,
                         QUAD4_SMEM);
    cudaFuncSetAttribute(k_feats_mma, cudaFuncAttributeMaxDynamicSharedMemorySize,
                         2 * STG_SZ);

    k_xsplit<<<(BATCH * D_IN) / 1024, 256>>>(x);
    k_wsplit<<<dim3(D_IN / 32, DF / 32), 256>>>(W);
    k_trinv<<<dim3(NMK, 8), 256>>>(covs);
    k_feats_mma<<<dim3(BATCH / 128, DF / 64), 256, 2 * STG_SZ>>>(bias);
    k_vprep<<<dim3(NMK, 4), 256>>>(means);
    k_prep<<<NMK, 32>>>(covs, weights);
    k_quad_mma<<<dim3(BATCH / 128, NMK / 2), 512, QUAD4_SMEM>>>(out);
}

// round 16
// speedup vs baseline: 1.0864x; 1.0864x over previous
#include <cuda_runtime.h>
#include <cuda_fp16.h>
#include <cstdint>
#include <math.h>

// Problem constants
#define BATCH 4096
#define D_IN  1024
#define DF    256
#define NM    10
#define NK    8
#define NMK   80
#define LOG2PI_F 1.8378770664093453f

// ---------------- scratch (no cudaMalloc allowed) ----------------
__device__ __align__(16) float  g_Ainv[NMK * DF * DF]; // fp32 L^-1 (upper zeroed)
__device__ __align__(16) __half g_xh[BATCH * D_IN];    // x fp16, [b][k]
__device__ __align__(16) __half g_Wh[DF * D_IN];       // W^T fp16, [n][k]
__device__ __align__(16) __half g_fh[BATCH * DF];      // feats fp16, [b][d]
__device__ __align__(16) __half g_Bh[NMK * DF * DF];   // Ainv fp16, [mk][d][k]
__device__ float g_v[NMK * DF];                         // Ainv @ mean (fp32, atomic)

// quad chunk schedule: 10 K=64 chunks, dblk-major
__constant__ int c_CD4[10] = {0, 1,1, 2,2,2, 3,3,3,3};
__constant__ int c_CK4[10] = {0, 0,1, 0,1,2, 0,1,2,3};

// ---------------- helpers ----------------
__device__ __forceinline__ uint32_t smem_u32(const void* p) {
    uint32_t a;
    asm("{ .reg .u64 t; cvta.to.shared.u64 t, %1; cvt.u32.u64 %0, t; }" : "=r"(a) : "l"(p));
    return a;
}

#define LDSM4(r, addr) \
    asm volatile("ldmatrix.sync.aligned.m8n8.x4.shared.b16 {%0,%1,%2,%3}, [%4];" \
        : "=r"((r)[0]), "=r"((r)[1]), "=r"((r)[2]), "=r"((r)[3]) : "r"(addr))

#define MMA16816(d, a, b) \
    asm volatile("mma.sync.aligned.m16n8k16.row.col.f32.f16.f16.f32 " \
        "{%0,%1,%2,%3},{%4,%5,%6,%7},{%8,%9},{%0,%1,%2,%3};" \
        : "+f"((d)[0]), "+f"((d)[1]), "+f"((d)[2]), "+f"((d)[3]) \
        : "r"((a)[0]), "r"((a)[1]), "r"((a)[2]), "r"((a)[3]), "r"((b)[0]), "r"((b)[1]))

#define CP16(saddr, gptr) \
    asm volatile("cp.async.cg.shared.global [%0], [%1], 16;" :: "r"(saddr), "l"(gptr) : "memory")
#define CP_COMMIT() asm volatile("cp.async.commit_group;" ::: "memory")
#define CP_WAIT1()  asm volatile("cp.async.wait_group 1;" ::: "memory")
#define CP_WAIT0()  asm volatile("cp.async.wait_group 0;" ::: "memory")

// feats stage buffer (24 KB per stage): F 128x128B @0, W 64x128B @16384
#define STG_SZ   24576
#define STG_FH   0
#define STG_WH   16384

// quad smem: persistent F [128 rows x 512B] @0 (64KB),
//            A ring 2 x 16KB @65536, V @98304 (512 f), Q @100352 (256 f),
//            C @101376 (c1[2], c2[2])
#define ST4_F    0
#define ST4_A    65536
#define A_STG_SZ 16384
#define OFQ4_V   98304
#define OFQ4_Q   100352
#define OFQ4_C   101376
#define QUAD4_SMEM 101504

// ---------------------------------------------------------------------------
// k_split: fused  x->fp16, W->W^T fp16, zero g_v.
// grid.x = 4096 (xsplit) + 256 (wsplit) + 20 (zero) = 4372
// ---------------------------------------------------------------------------
__global__ __launch_bounds__(256) void k_split(const float* __restrict__ x,
                                               const float* __restrict__ W)
{
    const int bx = blockIdx.x;
    if (bx < 4096) {
        size_t idx = ((size_t)bx * 256 + threadIdx.x) * 4;
        float4 v = *(const float4*)&x[idx];
        *(__half2*)&g_xh[idx]     = __floats2half2_rn(v.x, v.y);
        *(__half2*)&g_xh[idx + 2] = __floats2half2_rn(v.z, v.w);
    } else if (bx < 4352) {
        __shared__ float t[32][33];
        const int bi = bx - 4096;
        const int k0 = (bi & 31) * 32;
        const int n0 = (bi >> 5) * 32;
        const int tx = threadIdx.x & 31, ty = threadIdx.x >> 5;
#pragma unroll
        for (int i = 0; i < 4; i++)
            t[ty + i * 8][tx] = W[(size_t)(k0 + ty + i * 8) * DF + n0 + tx];
        __syncthreads();
#pragma unroll
        for (int i = 0; i < 4; i++) {
            int n = n0 + ty + i * 8;
            g_Wh[(size_t)n * D_IN + k0 + tx] = __float2half_rn(t[tx][ty + i * 8]);
        }
    } else {
        size_t idx = ((size_t)(bx - 4352) * 256 + threadIdx.x) * 4;
        *(float4*)&g_v[idx] = make_float4(0.f, 0.f, 0.f, 0.f);
    }
}

// ---------------------------------------------------------------------------
// k_trinv: triangular inverse of L = tril(covs[mk]); writes fp32 g_Ainv AND
// fp16 g_Bh (upper zeroed), and atomically accumulates v = Ainv @ mean.
// ---------------------------------------------------------------------------
__global__ __launch_bounds__(256) void k_trinv(const float* __restrict__ covs,
                                               const float* __restrict__ means)
{
    const int mk = blockIdx.x;
    const int cg = blockIdx.y;
    const int w = threadIdx.x >> 5;
    const int lane = threadIdx.x & 31;
    const int g = w * 8 + cg;
    const int j0 = g * 4;

    const float* L = covs + (size_t)mk * DF * DF;
    float* Ai = g_Ainv + (size_t)mk * DF * DF;
    __half* Bh = g_Bh + (size_t)mk * DF * DF;

    __shared__ float4 xck[8][DF];
    float4* xc = xck[w];

    for (int i = lane; i < j0; i += 32) {
        *(float4*)&Ai[i * DF + j0] = make_float4(0.f, 0.f, 0.f, 0.f);
        __half2 z2 = __floats2half2_rn(0.f, 0.f);
        *(__half2*)&Bh[i * DF + j0]     = z2;
        *(__half2*)&Bh[i * DF + j0 + 2] = z2;
    }

    for (int i = j0; i < DF; i++) {
        float4 s = make_float4(0.f, 0.f, 0.f, 0.f);
        for (int k = j0 + lane; k < i; k += 32) {
            float lik = L[i * DF + k];
            float4 xv = xc[k];
            s.x = fmaf(lik, xv.x, s.x);
            s.y = fmaf(lik, xv.y, s.y);
            s.z = fmaf(lik, xv.z, s.z);
            s.w = fmaf(lik, xv.w, s.w);
        }
#pragma unroll
        for (int off = 16; off > 0; off >>= 1) {
            s.x += __shfl_xor_sync(0xFFFFFFFFu, s.x, off);
            s.y += __shfl_xor_sync(0xFFFFFFFFu, s.y, off);
            s.z += __shfl_xor_sync(0xFFFFFFFFu, s.z, off);
            s.w += __shfl_xor_sync(0xFFFFFFFFu, s.w, off);
        }
        if (lane == 0) {
            float inv = 1.0f / L[i * DF + i];
            float4 xr;
            xr.x = ((i == j0 + 0 ? 1.0f : 0.0f) - s.x) * inv;
            xr.y = ((i == j0 + 1 ? 1.0f : 0.0f) - s.y) * inv;
            xr.z = ((i == j0 + 2 ? 1.0f : 0.0f) - s.z) * inv;
            xr.w = ((i == j0 + 3 ? 1.0f : 0.0f) - s.w) * inv;
            xc[i] = xr;
            *(float4*)&Ai[i * DF + j0] = xr;
            *(__half2*)&Bh[i * DF + j0]     = __floats2half2_rn(xr.x, xr.y);
            *(__half2*)&Bh[i * DF + j0 + 2] = __floats2half2_rn(xr.z, xr.w);
        }
        __syncwarp();
    }

    // fused vprep: this block owns columns j0..j0+3 -> contribute to v[i]
    __syncwarp();
    float4 m4 = *(const float4*)&means[mk * DF + j0];
    for (int i = j0 + lane; i < DF; i += 32) {
        float4 xv = xc[i];
        float p = xv.x * m4.x + xv.y * m4.y + xv.z * m4.z + xv.w * m4.w;
        atomicAdd(&g_v[mk * DF + i], p);
    }
}

// ---------------------------------------------------------------------------
// k_feats_mma: feats = relu(x @ W + b), single-pass fp16 warp-MMA. (unchanged)
// ---------------------------------------------------------------------------
__global__ __launch_bounds__(256) void k_feats_mma(const float* __restrict__ bias)
{
    extern __shared__ char sm[];
    const uint32_t smb = smem_u32(sm);
    const int tid = threadIdx.x;
    const int lane = tid & 31;
    const int wid = tid >> 5;
    const int warp_m = wid >> 1;
    const int warp_n = wid & 1;
    const int b0 = blockIdx.x * 128;
    const int n0 = blockIdx.y * 64;

    const __half* fh = g_xh + (size_t)b0 * D_IN;
    const __half* ah = g_Wh + (size_t)n0 * D_IN;

    const int aRow[2] = { warp_m * 32 +  0 + (lane & 7) + ((lane >> 3) & 1) * 8,
                          warp_m * 32 + 16 + (lane & 7) + ((lane >> 3) & 1) * 8 };
    const int aG = (lane >> 4) & 1;
    const int bRow[2] = { warp_n * 32 +  0 + (lane & 7) + ((lane >> 4) & 1) * 8,
                          warp_n * 32 + 16 + (lane & 7) + ((lane >> 4) & 1) * 8 };
    const int bG = (lane >> 3) & 1;
    const int aXor[2] = { aRow[0] & 7, aRow[1] & 7 };
    const int bXor[2] = { bRow[0] & 7, bRow[1] & 7 };

    auto stage = [&](int j) {
        const uint32_t sb = smb + (uint32_t)(j & 1) * STG_SZ;
        const int k0 = j * 64;
#pragma unroll
        for (int it = 0; it < 4; it++) {
            int slot = tid + it * 256;
            int row = slot >> 3, g = slot & 7;
            uint32_t off = (uint32_t)(row * 128 + ((g ^ (row & 7)) << 4));
            CP16(sb + STG_FH + off, fh + (size_t)row * D_IN + k0 + g * 8);
        }
#pragma unroll
        for (int it = 0; it < 2; it++) {
            int slot = tid + it * 256;
            int row = slot >> 3, g = slot & 7;
            uint32_t off = (uint32_t)(row * 128 + ((g ^ (row & 7)) << 4));
            CP16(sb + STG_WH + off, ah + (size_t)row * D_IN + k0 + g * 8);
        }
        CP_COMMIT();
    };

    float acc[2][4][4];
#pragma unroll
    for (int mt = 0; mt < 2; mt++)
#pragma unroll
        for (int nt = 0; nt < 4; nt++)
#pragma unroll
            for (int r = 0; r < 4; r++) acc[mt][nt][r] = 0.f;

    stage(0);
#pragma unroll 1
    for (int ci = 0; ci < 16; ci++) {
        if (ci + 1 < 16) { stage(ci + 1); CP_WAIT1(); } else { CP_WAIT0(); }
        __syncthreads();
        const uint32_t sb = smb + (uint32_t)(ci & 1) * STG_SZ;
#pragma unroll
        for (int ks = 0; ks < 4; ks++) {
            uint32_t fa[2][4], bm[2][4];
#pragma unroll
            for (int mt = 0; mt < 2; mt++) {
                uint32_t ga = (uint32_t)(((ks * 2 + aG) ^ aXor[mt]) << 4);
                LDSM4(fa[mt], sb + STG_FH + aRow[mt] * 128 + ga);
            }
#pragma unroll
            for (int pr = 0; pr < 2; pr++) {
                uint32_t gb = (uint32_t)(((ks * 2 + bG) ^ bXor[pr]) << 4);
                LDSM4(bm[pr], sb + STG_WH + bRow[pr] * 128 + gb);
            }
#pragma unroll
            for (int mt = 0; mt < 2; mt++)
#pragma unroll
                for (int nt = 0; nt < 4; nt++)
                    MMA16816(acc[mt][nt], fa[mt], &bm[nt >> 1][(nt & 1) * 2]);
        }
        __syncthreads();
    }

#pragma unroll
    for (int nt = 0; nt < 4; nt++) {
        int c = n0 + warp_n * 32 + nt * 8 + (lane & 3) * 2;
        float bc0 = bias[c], bc1 = bias[c + 1];
#pragma unroll
        for (int mt = 0; mt < 2; mt++) {
#pragma unroll
            for (int half = 0; half < 2; half++) {
                int row = b0 + warp_m * 32 + mt * 16 + (lane >> 2) + half * 8;
                float v0 = acc[mt][nt][half * 2 + 0] + bc0;
                float v1 = acc[mt][nt][half * 2 + 1] + bc1;
                v0 = v0 > 0.f ? v0 : 0.f;
                v1 = v1 > 0.f ? v1 : 0.f;
                *(__half2*)&g_fh[(size_t)row * DF + c] = __floats2half2_rn(v0, v1);
            }
        }
    }
}

// ---------------------------------------------------------------------------
// k_quad_mma (hot, launch #4 for ncu): fp16 warp-MMA + fused epilogue.
// R13 config: 256 thr, 8 warps (warp_m=wid>>1, warp_mk=wid&1), persistent F,
// A in 10 K=64 chunks, 2-stage ring, triangular skip.
// c1/c2 computed in-kernel (warps 0-1) from covs/weights.
// ---------------------------------------------------------------------------
__global__ __launch_bounds__(256, 2) void k_quad_mma(float* __restrict__ out,
                                                     const float* __restrict__ covs,
                                                     const float* __restrict__ weights)
{
    extern __shared__ char sm[];
    const uint32_t smb = smem_u32(sm);
    const int tid = threadIdx.x;
    const int lane = tid & 31;
    const int wid = tid >> 5;
    const int warp_m = wid >> 1;      // 0..3
    const int warp_mk = wid & 1;      // 0..1
    const int mk0 = blockIdx.y * 2;
    const int b0 = blockIdx.x * 128;

    ((float*)(sm + OFQ4_V))[tid]       = g_v[mk0 * DF + tid];
    ((float*)(sm + OFQ4_V))[256 + tid] = g_v[(mk0 + 1) * DF + tid];

    const __half* fh = g_fh + (size_t)b0 * DF;
    const __half* ap[2] = { g_Bh + (size_t)mk0 * DF * DF,
                            g_Bh + (size_t)(mk0 + 1) * DF * DF };

    // ---- stage persistent F: 128 rows x 32 groups of 16B, swizzled ----
#pragma unroll
    for (int it = 0; it < 16; it++) {
        int u = tid + it * 256;          // 0..4095
        int r = u >> 5, g = u & 31;
        uint32_t off = (uint32_t)(r * 512 + (((g & 24) | ((g & 7) ^ (r & 7))) << 4));
        CP16(smb + ST4_F + off, fh + (size_t)r * DF + g * 8);
    }
    CP_COMMIT();

    // ---- in-kernel c1/c2 (warps 0-1, one mk each), overlaps cp.async ----
    if (wid < 2) {
        const int mk = mk0 + wid;
        const float* L = covs + (size_t)mk * DF * DF;
        float logdet = 0.0f;
        for (int i = lane; i < DF; i += 32)
            logdet += logf(L[i * DF + i]);
#pragma unroll
        for (int off = 16; off > 0; off >>= 1)
            logdet += __shfl_xor_sync(0xFFFFFFFFu, logdet, off);
        if (lane == 0) {
            const int m = mk >> 3;
            float wk[NK];
            float mx = -1e30f;
#pragma unroll
            for (int j = 0; j < NK; j++) { wk[j] = weights[m * NK + j]; mx = fmaxf(mx, wk[j]); }
            float sum = 0.f;
#pragma unroll
            for (int j = 0; j < NK; j++) sum += expf(wk[j] - mx);
            float wsm = expf(weights[mk] - mx) / sum;
            float* sc = (float*)(sm + OFQ4_C);
            sc[wid]     = -0.5f * wsm;                                   // c1
            sc[2 + wid] = wsm * (-0.5f * (float)DF * LOG2PI_F) - wsm * logdet; // c2
        }
    }

    // F ldmatrix lane addressing
    int rA[2];
#pragma unroll
    for (int mt = 0; mt < 2; mt++)
        rA[mt] = warp_m * 32 + mt * 16 + (lane & 7) + ((lane >> 3) & 1) * 8;
    const int gselA = (lane >> 4) & 1;

    // A ldmatrix lane addressing (64 rows x 128B, classic swizzle)
    int rB[4];
#pragma unroll
    for (int pr = 0; pr < 4; pr++)
        rB[pr] = pr * 16 + (lane & 7) + ((lane >> 4) & 1) * 8;
    const int gselB = (lane >> 3) & 1;

    auto stageA = [&](int j) {
        const uint32_t sb = smb + ST4_A + (uint32_t)(j & 1) * A_STG_SZ;
        const int k0 = c_CK4[j] * 64;
        const int ar0 = c_CD4[j] * 64;
        const bool diag = (c_CK4[j] == c_CD4[j]);
#pragma unroll
        for (int it = 0; it < 4; it++) {
            int u = tid + it * 256;             // 0..1023
            int mki = u >> 9;
            int v = u & 511;
            int r = v >> 3, g = v & 7;
            if (!diag || ((g >> 1) <= (r >> 4))) {
                uint32_t off = (uint32_t)(r * 128 + ((g ^ (r & 7)) << 4));
                CP16(sb + mki * 8192 + off,
                     ap[mki] + (size_t)(ar0 + r) * DF + k0 + g * 8);
            }
        }
        CP_COMMIT();
    };

    float qrow[4] = {0.f, 0.f, 0.f, 0.f};
    const float* vptr = (const float*)(sm + OFQ4_V) + warp_mk * DF;

    stageA(0);
    int ci = 0;
#pragma unroll 1
    for (int dblk = 0; dblk < 4; dblk++) {
        const int nrow0 = dblk * 64;
        const int nch = dblk + 1;
        float acc[2][8][4];
#pragma unroll
        for (int mt = 0; mt < 2; mt++)
#pragma unroll
            for (int nt = 0; nt < 8; nt++)
#pragma unroll
                for (int r = 0; r < 4; r++) acc[mt][nt][r] = 0.f;

#pragma unroll 1
        for (int kc = 0; kc < nch; kc++) {
            if (ci + 1 < 10) { stageA(ci + 1); CP_WAIT1(); } else { CP_WAIT0(); }
            __syncthreads();
            const uint32_t sbA = smb + ST4_A + (uint32_t)(ci & 1) * A_STG_SZ
                               + (uint32_t)warp_mk * 8192;
            const int ck = c_CK4[ci];
            const bool diag = (kc == nch - 1);
#pragma unroll
            for (int ks = 0; ks < 4; ks++) {
                uint32_t fa[2][4];
#pragma unroll
                for (int mt = 0; mt < 2; mt++) {
                    int g = ck * 8 + ks * 2 + gselA;
                    uint32_t off = (uint32_t)(rA[mt] * 512 +
                        (((g & 24) | ((g & 7) ^ (rA[mt] & 7))) << 4));
                    LDSM4(fa[mt], smb + ST4_F + off);
                }
#pragma unroll
                for (int pr = 0; pr < 4; pr++) {
                    if (!diag || pr >= ks) {
                        uint32_t bm[4];
                        uint32_t offb = (uint32_t)(rB[pr] * 128 +
                            (((ks * 2 + gselB) ^ (rB[pr] & 7)) << 4));
                        LDSM4(bm, sbA + offb);
#pragma unroll
                        for (int mt = 0; mt < 2; mt++)
#pragma unroll
                            for (int j2 = 0; j2 < 2; j2++)
                                MMA16816(acc[mt][pr * 2 + j2], fa[mt], &bm[j2 * 2]);
                    }
                }
            }
            __syncthreads();
            ci++;
        }

        // fold: z = D - v[d]; qrow += z^2
#pragma unroll
        for (int mt = 0; mt < 2; mt++)
#pragma unroll
            for (int nt = 0; nt < 8; nt++) {
#pragma unroll
                for (int r = 0; r < 4; r++) {
                    int d = nrow0 + nt * 8 + (lane & 3) * 2 + (r & 1);
                    float z = acc[mt][nt][r] - vptr[d];
                    qrow[mt * 2 + (r >> 1)] = fmaf(z, z, qrow[mt * 2 + (r >> 1)]);
                }
            }
    }

    float* qs = (float*)(sm + OFQ4_Q);
#pragma unroll
    for (int i = 0; i < 4; i++) {
        float q = qrow[i];
        q += __shfl_xor_sync(0xFFFFFFFFu, q, 1);
        q += __shfl_xor_sync(0xFFFFFFFFu, q, 2);
        if ((lane & 3) == 0)
            qs[warp_mk * 128 + warp_m * 32 + (i >> 1) * 16 + (i & 1) * 8 + (lane >> 2)] = q;
    }
    __syncthreads();
    {
        const float* sc = (const float*)(sm + OFQ4_C);
        int mkloc = tid >> 7;
        int row = tid & 127;
        int mk = mk0 + mkloc;
        out[(size_t)(b0 + row) * NMK + mk] =
            fmaf(sc[mkloc], qs[mkloc * 128 + row], sc[2 + mkloc]);
    }
}

// ---------------------------------------------------------------------------
extern "C" void kernel_launch(void* const* d_in, const int* in_sizes, int n_in,
                              void* d_out, int out_size)
{
    const float* x       = (const float*)d_in[0];
    const float* W       = (const float*)d_in[1];
    const float* bias    = (const float*)d_in[2];
    const float* means   = (const float*)d_in[3];
    const float* covs    = (const float*)d_in[4];
    const float* weights = (const float*)d_in[5];
    float* out = (float*)d_out;

    cudaFuncSetAttribute(k_quad_mma, cudaFuncAttributeMaxDynamicSharedMemorySize,
                         QUAD4_SMEM);
    cudaFuncSetAttribute(k_feats_mma, cudaFuncAttributeMaxDynamicSharedMemorySize,
                         2 * STG_SZ);

    k_split<<<4372, 256>>>(x, W);
    k_trinv<<<dim3(NMK, 8), 256>>>(covs, means);
    k_feats_mma<<<dim3(BATCH / 128, DF / 64), 256, 2 * STG_SZ>>>(bias);
    k_quad_mma<<<dim3(BATCH / 128, NMK / 2), 256, QUAD4_SMEM>>>(out, covs, weights);
}